// round 6
// baseline (speedup 1.0000x reference)
#include <cuda_runtime.h>

// PEquiNN: o_x = l_xx*X + (g_xx*rowsum(X) + g_yx*rowsum(Y)) per row
//          o_y = l_yy*Y + (g_yy*rowsum(Y) + g_xy*rowsum(X)) per row
// X, Y: [8192, 4096] f32. Single-pass streaming: 256 MiB read + 256 MiB write
// (provably minimal). Binding constraint: DRAM r/w-mix efficiency (~80% of
// 8 TB/s spec across all 4 layout/hint cells tested).
//
// R6: persistent grid. 592 CTAs (148 SMs x occ 4) x 512 threads, each CTA
// strides over rows. Removes 14 wave transitions + 7600 CTA dispatch setups,
// and gives each CTA a consecutive-row (more page-sequential) DRAM stream.
// Split-warp layout (warps 0-7 = X half, 8-15 = Y half), plain ld/st
// (hints measurably hurt DRAM% in R2/R3).

#define N_COLS 4096
#define VEC_PER_ROW (N_COLS / 4)       // 1024 float4 per row
#define THREADS 512
#define HALF 256                        // threads per matrix half
#define V_PER_THREAD (VEC_PER_ROW / HALF)  // 4 float4 = 16 floats per thread
#define GRID_CTAS (148 * 4)

__global__ __launch_bounds__(THREADS)
void peq_kernel(const float4* __restrict__ X,
                const float4* __restrict__ Y,
                const float* __restrict__ p_lxx,
                const float* __restrict__ p_lyy,
                const float* __restrict__ p_gxx,
                const float* __restrict__ p_gxy,
                const float* __restrict__ p_gyx,
                const float* __restrict__ p_gyy,
                float4* __restrict__ OX,
                float4* __restrict__ OY,
                int rows)
{
    const int tid = threadIdx.x;
    const int half_tid = tid & (HALF - 1);   // 0..255 within the half
    const bool is_y = tid >= HALF;           // warps 8-15 handle Y

    const float4* __restrict__ SRC = is_y ? Y : X;
    float4* __restrict__ DST = is_y ? OY : OX;

    // Scalars: load once per CTA (not per row).
    const float lxx = __ldg(p_lxx);
    const float lyy = __ldg(p_lyy);
    const float gxx = __ldg(p_gxx);
    const float gxy = __ldg(p_gxy);
    const float gyx = __ldg(p_gyx);
    const float gyy = __ldg(p_gyy);
    const float l = is_y ? lyy : lxx;

    __shared__ float ssum[THREADS / 32];     // 16 entries
    const int wid = tid >> 5;

    for (int row = blockIdx.x; row < rows; row += GRID_CTAS) {
        const size_t base = (size_t)row * VEC_PER_ROW + half_tid;

        // Load this half-row into registers; accumulate partial sum.
        float4 v[V_PER_THREAD];
        float s = 0.f;
#pragma unroll
        for (int i = 0; i < V_PER_THREAD; i++) {
            v[i] = SRC[base + i * HALF];
            s += (v[i].x + v[i].y) + (v[i].z + v[i].w);
        }

        // Warp reduce.
#pragma unroll
        for (int o = 16; o > 0; o >>= 1)
            s += __shfl_xor_sync(0xFFFFFFFFu, s, o);

        // Cross-warp: warps 0-7 carry X partials, 8-15 carry Y partials.
        if ((tid & 31) == 0) ssum[wid] = s;
        __syncthreads();

        float sx = 0.f, sy = 0.f;
#pragma unroll
        for (int i = 0; i < 8; i++)  sx += ssum[i];
#pragma unroll
        for (int i = 8; i < 16; i++) sy += ssum[i];

        const float b = is_y ? (gyy * sy + gxy * sx)
                             : (gxx * sx + gyx * sy);

#pragma unroll
        for (int i = 0; i < V_PER_THREAD; i++) {
            float4 o;
            o.x = fmaf(l, v[i].x, b);
            o.y = fmaf(l, v[i].y, b);
            o.z = fmaf(l, v[i].z, b);
            o.w = fmaf(l, v[i].w, b);
            DST[base + i * HALF] = o;
        }

        // ssum is rewritten next iteration; ensure all warps consumed it.
        __syncthreads();
    }
}

extern "C" void kernel_launch(void* const* d_in, const int* in_sizes, int n_in,
                              void* d_out, int out_size)
{
    const float4* X = (const float4*)d_in[0];
    const float4* Y = (const float4*)d_in[1];
    const float* lxx = (const float*)d_in[2];
    const float* lyy = (const float*)d_in[3];
    const float* gxx = (const float*)d_in[4];
    const float* gxy = (const float*)d_in[5];
    const float* gyx = (const float*)d_in[6];
    const float* gyy = (const float*)d_in[7];

    const int total = in_sizes[0];          // R * N = 8192 * 4096
    const int rows = total / N_COLS;        // 8192

    float* out = (float*)d_out;
    float4* OX = (float4*)out;                          // o_x first
    float4* OY = (float4*)(out + (size_t)total);        // o_y second

    peq_kernel<<<GRID_CTAS, THREADS>>>(X, Y, lxx, lyy, gxx, gxy, gyx, gyy,
                                       OX, OY, rows);
}